// round 3
// baseline (speedup 1.0000x reference)
#include <cuda_runtime.h>
#include <cstdint>

// Inverse 2D Haar DWT, fused elementwise butterfly (matrices folded to constants).
// Inputs: LL, LH, HL, HH : [B=16, C=64, 128, 128] f32. Output: [B, C, 256, 256] f32.
//
// out[2i,   2j]   = 0.5*(LL - LH - HL + HH)
// out[2i,   2j+1] = 0.5*(LL + LH - HL - HH)
// out[2i+1, 2j]   = 0.5*(LL - LH + HL - HH)
// out[2i+1, 2j+1] = 0.5*(LL + LH + HL + HH)
//
// R3: persistent grid-stride kernel (single wave: 148 SMs x 8 CTAs) to remove
// wave-transition overhead; R1's thread mapping and default cache operators
// (both .cs hints and MLP=8 restructure measured neutral/negative in R2).

static constexpr int H_IN  = 128;
static constexpr int W_IN  = 128;
static constexpr int PLANE_IN  = H_IN * W_IN;        // 16384
static constexpr int PLANE_OUT = 4 * PLANE_IN;       // 65536
static constexpr int W_OUT = 2 * W_IN;               // 256

// work item = one float2 (2 adjacent j) of one input row
// items per plane = 128 rows * 64 float2-cols = 8192
static constexpr int ITEMS_PER_PLANE = H_IN * (W_IN / 2);  // 8192

__device__ __forceinline__ void butterfly(float2 a, float2 b, float2 c, float2 d,
                                          float4& r0, float4& r1)
{
    r0.x = 0.5f * (a.x - b.x - c.x + d.x);
    r0.y = 0.5f * (a.x + b.x - c.x - d.x);
    r1.x = 0.5f * (a.x - b.x + c.x - d.x);
    r1.y = 0.5f * (a.x + b.x + c.x + d.x);
    r0.z = 0.5f * (a.y - b.y - c.y + d.y);
    r0.w = 0.5f * (a.y + b.y - c.y - d.y);
    r1.z = 0.5f * (a.y - b.y + c.y - d.y);
    r1.w = 0.5f * (a.y + b.y + c.y + d.y);
}

__global__ void __launch_bounds__(256, 8)
idwt_haar_kernel(const float* __restrict__ LL,
                 const float* __restrict__ LH,
                 const float* __restrict__ HL,
                 const float* __restrict__ HH,
                 float* __restrict__ out,
                 unsigned int n_items)
{
    const unsigned int stride = gridDim.x * blockDim.x;

    #pragma unroll 2
    for (unsigned int idx = blockIdx.x * blockDim.x + threadIdx.x;
         idx < n_items; idx += stride)
    {
        const unsigned int plane = idx >> 13;          // / 8192
        const unsigned int rem   = idx & 8191;
        const unsigned int row   = rem >> 6;           // input row i
        const unsigned int col2  = rem & 63;           // float2 column index

        const int64_t in_off  = (int64_t)plane * PLANE_IN  + row * W_IN + col2 * 2;
        const int64_t out_off = (int64_t)plane * PLANE_OUT
                              + (int64_t)(2 * row) * W_OUT + col2 * 4;

        const float2 a = *reinterpret_cast<const float2*>(LL + in_off);
        const float2 b = *reinterpret_cast<const float2*>(LH + in_off);
        const float2 c = *reinterpret_cast<const float2*>(HL + in_off);
        const float2 d = *reinterpret_cast<const float2*>(HH + in_off);

        float4 r0, r1;
        butterfly(a, b, c, d, r0, r1);

        *reinterpret_cast<float4*>(out + out_off)         = r0;
        *reinterpret_cast<float4*>(out + out_off + W_OUT) = r1;
    }
}

extern "C" void kernel_launch(void* const* d_in, const int* in_sizes, int n_in,
                              void* d_out, int out_size)
{
    const float* LL = (const float*)d_in[0];
    const float* LH = (const float*)d_in[1];
    const float* HL = (const float*)d_in[2];
    const float* HH = (const float*)d_in[3];
    float* out = (float*)d_out;

    const int64_t n_elems = (int64_t)in_sizes[0];
    const int64_t planes  = n_elems / PLANE_IN;
    const unsigned int n_items = (unsigned int)(planes * ITEMS_PER_PLANE);

    // One full wave: 148 SMs x 8 CTAs/SM (occupancy-limited by __launch_bounds__).
    const int block = 256;
    const int grid  = 148 * 8;

    idwt_haar_kernel<<<grid, block>>>(LL, LH, HL, HH, out, n_items);
}

// round 6
// speedup vs baseline: 1.1089x; 1.1089x over previous
#include <cuda_runtime.h>
#include <cstdint>

// Inverse 2D Haar DWT, fused elementwise butterfly (matrices folded to constants).
// Inputs: LL, LH, HL, HH : [B=16, C=64, 128, 128] f32. Output: [B, C, 256, 256] f32.
//
// out[2i,   2j]   = 0.5*(LL - LH - HL + HH)
// out[2i,   2j+1] = 0.5*(LL + LH - HL - HH)
// out[2i+1, 2j]   = 0.5*(LL - LH + HL - HH)
// out[2i+1, 2j+1] = 0.5*(LL + LH + HL + HH)
//
// R4: R1's exact structure (flat grid, best measured: 81.1us, DRAM 82.4%)
// + streaming hint on STORES ONLY (st.global.cs): output lines are written
// once and never re-read, evict-first lets L2 schedule writebacks early.
// (R2's combined ld.cs+st.cs+remap was confounded; R3's grid-stride lost MLP.)

static constexpr int H_IN  = 128;
static constexpr int W_IN  = 128;
static constexpr int PLANE_IN  = H_IN * W_IN;        // 16384
static constexpr int PLANE_OUT = 4 * PLANE_IN;       // 65536
static constexpr int W_OUT = 2 * W_IN;               // 256

// Each thread handles one float2 (2 adjacent j) of one input row
// -> writes one float4 in each of two adjacent output rows.
static constexpr int THREADS_PER_PLANE = H_IN * (W_IN / 2);  // 8192

__device__ __forceinline__ void stcs4(float* p, float4 v) {
    asm volatile("st.global.cs.v4.f32 [%0], {%1,%2,%3,%4};"
                 :: "l"(p), "f"(v.x), "f"(v.y), "f"(v.z), "f"(v.w));
}

__global__ void __launch_bounds__(256, 8)
idwt_haar_kernel(const float* __restrict__ LL,
                 const float* __restrict__ LH,
                 const float* __restrict__ HL,
                 const float* __restrict__ HH,
                 float* __restrict__ out)
{
    const int64_t gtid = (int64_t)blockIdx.x * blockDim.x + threadIdx.x;

    const int plane = (int)(gtid >> 13);           // / 8192
    const int rem   = (int)(gtid & 8191);
    const int row   = rem >> 6;                    // / 64  -> input row i
    const int col2  = rem & 63;                    // float2 column index

    const int64_t in_off  = (int64_t)plane * PLANE_IN + row * W_IN + col2 * 2;
    const int64_t out_off = (int64_t)plane * PLANE_OUT + (int64_t)(2 * row) * W_OUT + col2 * 4;

    const float2 a = *reinterpret_cast<const float2*>(LL + in_off);
    const float2 b = *reinterpret_cast<const float2*>(LH + in_off);
    const float2 c = *reinterpret_cast<const float2*>(HL + in_off);
    const float2 d = *reinterpret_cast<const float2*>(HH + in_off);

    float4 r0, r1;  // row 2i and row 2i+1, 4 consecutive output columns each

    // element 0 (j = 2*col2)
    {
        const float pa = a.x, pb = b.x, pc = c.x, pd = d.x;
        r0.x = 0.5f * (pa - pb - pc + pd);
        r0.y = 0.5f * (pa + pb - pc - pd);
        r1.x = 0.5f * (pa - pb + pc - pd);
        r1.y = 0.5f * (pa + pb + pc + pd);
    }
    // element 1 (j = 2*col2 + 1)
    {
        const float pa = a.y, pb = b.y, pc = c.y, pd = d.y;
        r0.z = 0.5f * (pa - pb - pc + pd);
        r0.w = 0.5f * (pa + pb - pc - pd);
        r1.z = 0.5f * (pa - pb + pc - pd);
        r1.w = 0.5f * (pa + pb + pc + pd);
    }

    stcs4(out + out_off,         r0);
    stcs4(out + out_off + W_OUT, r1);
}

extern "C" void kernel_launch(void* const* d_in, const int* in_sizes, int n_in,
                              void* d_out, int out_size)
{
    const float* LL = (const float*)d_in[0];
    const float* LH = (const float*)d_in[1];
    const float* HL = (const float*)d_in[2];
    const float* HH = (const float*)d_in[3];
    float* out = (float*)d_out;

    const int64_t n_elems  = (int64_t)in_sizes[0];
    const int64_t planes   = n_elems / PLANE_IN;
    const int64_t nthreads = planes * THREADS_PER_PLANE;

    const int block = 256;
    const int grid  = (int)((nthreads + block - 1) / block);

    idwt_haar_kernel<<<grid, block>>>(LL, LH, HL, HH, out);
}

// round 7
// speedup vs baseline: 1.1107x; 1.0016x over previous
#include <cuda_runtime.h>
#include <cstdint>

// Inverse 2D Haar DWT, fused elementwise butterfly (matrices folded to constants).
// Inputs: LL, LH, HL, HH : [B=16, C=64, 128, 128] f32. Output: [B, C, 256, 256] f32.
//
// out[2i,   2j]   = 0.5*(LL - LH - HL + HH)
// out[2i,   2j+1] = 0.5*(LL + LH - HL - HH)
// out[2i+1, 2j]   = 0.5*(LL - LH + HL - HH)
// out[2i+1, 2j+1] = 0.5*(LL + LH + HL + HH)
//
// FINAL (R7): revert to R1 — empirically the fastest of 5 measured variants
// (81.1us, DRAM 82.4%, HBM 6530 GB/s). Streaming hints (ld.cs/st.cs), MLP=8
// restructure, and persistent grid-stride all measured neutral or negative;
// the kernel sits at the HBM3e mixed read/write stream floor. Only change vs
// R1: 32-bit index arithmetic (8.4M threads < 2^32).

static constexpr int H_IN  = 128;
static constexpr int W_IN  = 128;
static constexpr int PLANE_IN  = H_IN * W_IN;        // 16384
static constexpr int PLANE_OUT = 4 * PLANE_IN;       // 65536
static constexpr int W_OUT = 2 * W_IN;               // 256

// Each thread handles one float2 (2 adjacent j) of one input row
// -> writes one float4 in each of two adjacent output rows.
static constexpr int THREADS_PER_PLANE = H_IN * (W_IN / 2);  // 8192

__global__ void __launch_bounds__(256, 8)
idwt_haar_kernel(const float* __restrict__ LL,
                 const float* __restrict__ LH,
                 const float* __restrict__ HL,
                 const float* __restrict__ HH,
                 float* __restrict__ out)
{
    const unsigned int gtid = blockIdx.x * blockDim.x + threadIdx.x;

    const unsigned int plane = gtid >> 13;         // / 8192
    const unsigned int rem   = gtid & 8191u;
    const unsigned int row   = rem >> 6;           // input row i
    const unsigned int col2  = rem & 63u;          // float2 column index

    const unsigned int in_off  = plane * PLANE_IN + row * W_IN + col2 * 2;
    const unsigned int out_off = plane * PLANE_OUT + (2u * row) * W_OUT + col2 * 4;

    const float2 a = *reinterpret_cast<const float2*>(LL + in_off);
    const float2 b = *reinterpret_cast<const float2*>(LH + in_off);
    const float2 c = *reinterpret_cast<const float2*>(HL + in_off);
    const float2 d = *reinterpret_cast<const float2*>(HH + in_off);

    float4 r0, r1;  // row 2i and row 2i+1, 4 consecutive output columns each

    // element 0 (j = 2*col2)
    {
        const float pa = a.x, pb = b.x, pc = c.x, pd = d.x;
        r0.x = 0.5f * (pa - pb - pc + pd);
        r0.y = 0.5f * (pa + pb - pc - pd);
        r1.x = 0.5f * (pa - pb + pc - pd);
        r1.y = 0.5f * (pa + pb + pc + pd);
    }
    // element 1 (j = 2*col2 + 1)
    {
        const float pa = a.y, pb = b.y, pc = c.y, pd = d.y;
        r0.z = 0.5f * (pa - pb - pc + pd);
        r0.w = 0.5f * (pa + pb - pc - pd);
        r1.z = 0.5f * (pa - pb + pc - pd);
        r1.w = 0.5f * (pa + pb + pc + pd);
    }

    *reinterpret_cast<float4*>(out + out_off)         = r0;
    *reinterpret_cast<float4*>(out + out_off + W_OUT) = r1;
}

extern "C" void kernel_launch(void* const* d_in, const int* in_sizes, int n_in,
                              void* d_out, int out_size)
{
    const float* LL = (const float*)d_in[0];
    const float* LH = (const float*)d_in[1];
    const float* HL = (const float*)d_in[2];
    const float* HH = (const float*)d_in[3];
    float* out = (float*)d_out;

    const int64_t n_elems  = (int64_t)in_sizes[0];
    const int64_t planes   = n_elems / PLANE_IN;
    const int64_t nthreads = planes * THREADS_PER_PLANE;

    const int block = 256;
    const int grid  = (int)((nthreads + block - 1) / block);

    idwt_haar_kernel<<<grid, block>>>(LL, LH, HL, HH, out);
}